// round 6
// baseline (speedup 1.0000x reference)
#include <cuda_runtime.h>

#define MODES 64
#define AUD   16
#define T     32768
#define F     4096
#define NC    513

// ---------------- device scratch ----------------
__device__ float  g_amp[AUD * MODES];
__device__ float  g_Ec[MODES * NC], g_Sc[MODES * NC], g_Cc[MODES * NC];
__device__ float  g_Ef[MODES * 64], g_Sf[MODES * 64], g_Cf[MODES * 64];
__device__ float  g_Ecp[MODES * 64], g_Efp[MODES * 64];   // e^{+d n} coarse/fine
__device__ float  g_Ps[MODES * T], g_Pc[MODES * T];
__device__ float  g_Rc[MODES * F], g_Rs[MODES * F];       // cos/sin(w tau) e^{+d tau}
__device__ float  g_s0[AUD * 512];                        // early signal
__device__ float2 g_ABp[MODES * AUD * 8];                 // lag-chunk partials
__device__ float2 g_cum[8 * MODES * AUD];                 // amp-scaled prefix
__device__ float  g_dpart[AUD * F];                       // diagonal conv part

// ---------------- K1: params + trig/exp tables ----------------
__global__ void k_tables(const float* __restrict__ freq_linear,
                         const float* __restrict__ amp_value,
                         const float* __restrict__ alpha_params,
                         const float* __restrict__ beta_params)
{
    int m = blockIdx.x;
    int tid = threadIdx.x;          // 128
    __shared__ float s_a[64], s_aw[64], s_b[64], s_bw[64];
    __shared__ float s_d, s_w;

    const float la0 = logf(0.6f), la1 = logf(60.0f);
    const float lb0 = logf(2e-8f), lb1 = logf(2e-6f);

    if (tid < 64) {
        float frac = (float)tid / 63.0f;
        float va = expf(la0 + (la1 - la0) * frac);
        float vb = expf(lb0 + (lb1 - lb0) * frac);
        float spa = log1pf(expf(alpha_params[m * 64 + tid]));
        float spb = log1pf(expf(beta_params [m * 64 + tid]));
        s_a[tid] = spa * va; s_aw[tid] = spa;
        s_b[tid] = spb * vb; s_bw[tid] = spb;
    } else if (tid < 80) {
        int a = tid - 64;
        float x = amp_value[a * MODES + m];
        float s = 1.0f / (1.0f + expf(-x));
        g_amp[a * MODES + m] = 2.0f * expf(2.30258509299404568f * logf(s)) + 1e-7f;
    }
    __syncthreads();
    if (tid == 0) {
        float asum = 0.f, awsum = 0.f, bsum = 0.f, bwsum = 0.f;
        for (int b = 0; b < 64; b++) {
            asum += s_a[b]; awsum += s_aw[b];
            bsum += s_b[b]; bwsum += s_bw[b];
        }
        float alpha = asum / awsum, beta = bsum / bwsum;
        float f2pi = freq_linear[m] * 6.28318530717958647692f;
        float lbd  = f2pi * f2pi;
        float dr   = 0.5f * (alpha + beta * lbd);
        s_d = dr / 16000.0f;
        s_w = sqrtf(lbd - dr * dr) / 16000.0f;
    }
    __syncthreads();
    float d = s_d, w = s_w;
    for (int i = tid; i < NC; i += 128) {
        float n = (float)(i << 6);
        float s, c;
        sincosf(w * n, &s, &c);
        g_Ec[m * NC + i] = expf(-d * n);
        g_Sc[m * NC + i] = s;
        g_Cc[m * NC + i] = c;
    }
    if (tid < 64) {
        float n = (float)tid;
        float s, c;
        sincosf(w * n, &s, &c);
        g_Ef[m * 64 + tid] = expf(-d * n);
        g_Sf[m * 64 + tid] = s;
        g_Cf[m * 64 + tid] = c;
        g_Ecp[m * 64 + tid] = expf(d * (float)(tid << 6));
        g_Efp[m * 64 + tid] = expf(d * n);
    }
}

// ---------------- K2: Ps/Pc + Rc/Rs + early signal ----------------
__global__ void __launch_bounds__(256) k_fill()
{
    __shared__ float samp[AUD * MODES];
    int b = blockIdx.x, tid = threadIdx.x;

    if (b < 8192) {
        // Ps/Pc:  n = t+1
        int m = b >> 7, t = (b & 127) * 256 + tid;
        int n = t + 1;
        int c = n >> 6, r = n & 63;
        float Ec = g_Ec[m * NC + c], Sc = g_Sc[m * NC + c], Cc = g_Cc[m * NC + c];
        float Ef = g_Ef[m * 64 + r], Sf = g_Sf[m * 64 + r], Cf = g_Cf[m * 64 + r];
        float E  = Ec * Ef;
        g_Ps[m * T + t] = E * (Sc * Cf + Cc * Sf);
        g_Pc[m * T + t] = E * (Cc * Cf - Sc * Sf);
    } else if (b < 9216) {
        // Rc/Rs at lag tau: e^{+d tau} * cos/sin(w tau)
        int b2 = b - 8192;
        int m = b2 >> 4, k = (b2 & 15) * 256 + tid;
        int c = k >> 6, r = k & 63;
        float Sc = g_Sc[m * NC + c], Cc = g_Cc[m * NC + c];
        float Sf = g_Sf[m * 64 + r], Cf = g_Cf[m * 64 + r];
        float Ep = g_Ecp[m * 64 + c] * g_Efp[m * 64 + r];
        g_Rc[m * F + k] = Ep * (Cc * Cf - Sc * Sf);
        g_Rs[m * F + k] = Ep * (Sc * Cf + Cc * Sf);
    } else {
        // early signal s0[a][j], j < 512
        for (int i = tid; i < AUD * MODES; i += 256) samp[i] = g_amp[i];
        __syncthreads();
        int j = (b - 9216) * 256 + tid;
        int n = j + 1, c = n >> 6, r = n & 63;
        float acc[AUD];
        #pragma unroll
        for (int a = 0; a < AUD; a++) acc[a] = 0.f;
        #pragma unroll 4
        for (int m = 0; m < MODES; m++) {
            float Ec = g_Ec[m * NC + c], Sc = g_Sc[m * NC + c], Cc = g_Cc[m * NC + c];
            float Ef = g_Ef[m * 64 + r], Sf = g_Sf[m * 64 + r], Cf = g_Cf[m * 64 + r];
            float ps = Ec * Ef * (Sc * Cf + Cc * Sf);
            #pragma unroll
            for (int a = 0; a < AUD; a++)
                acc[a] = fmaf(samp[a * MODES + m], ps, acc[a]);
        }
        #pragma unroll
        for (int a = 0; a < AUD; a++)
            g_s0[a * 512 + j] = acc[a];
    }
}

// ---------------- K3 merged: lag-chunk partials (0..511) + diagonal conv (512..575) ----------------
__global__ void __launch_bounds__(256) k_chunks(const float* __restrict__ forces)
{
    __shared__ float sm[3072];   // 12KB
    int b = blockIdx.x, tid = threadIdx.x;

    if (b < 512) {
        // A_am[c] = sum_{tau in chunk} g[tau]*Rc[m,tau],  g[tau] = forces[4095-tau]
        int m = b >> 3, c = b & 7, k0 = c << 9;
        float* sRc = sm;
        float* sRs = sm + 512;
        sRc[tid]       = g_Rc[m * F + k0 + tid];
        sRc[tid + 256] = g_Rc[m * F + k0 + tid + 256];
        sRs[tid]       = g_Rs[m * F + k0 + tid];
        sRs[tid + 256] = g_Rs[m * F + k0 + tid + 256];
        __syncthreads();

        int wrp = tid >> 5, lane = tid & 31;
        int a0 = wrp * 2, a1 = a0 + 1;
        const float* f0 = forces + a0 * F + 4095 - k0;   // f0[-tau_local]
        const float* f1 = forces + a1 * F + 4095 - k0;
        float A0 = 0.f, B0 = 0.f, A1 = 0.f, B1 = 0.f;
        #pragma unroll 4
        for (int k = lane; k < 512; k += 32) {
            float rc = sRc[k], rs = sRs[k];
            float x0 = f0[-k], x1 = f1[-k];
            A0 = fmaf(x0, rc, A0); B0 = fmaf(x0, rs, B0);
            A1 = fmaf(x1, rc, A1); B1 = fmaf(x1, rs, B1);
        }
        #pragma unroll
        for (int o = 16; o; o >>= 1) {
            A0 += __shfl_xor_sync(0xffffffffu, A0, o);
            B0 += __shfl_xor_sync(0xffffffffu, B0, o);
            A1 += __shfl_xor_sync(0xffffffffu, A1, o);
            B1 += __shfl_xor_sync(0xffffffffu, B1, o);
        }
        if (lane == 0) {
            g_ABp[(m * AUD + a0) * 8 + c] = make_float2(A0, B0);
            g_ABp[(m * AUD + a1) * 8 + c] = make_float2(A1, B1);
        }
    } else {
        // diagonal: out_diag[a][ti*512+u] = sum_{v=0}^{u} g[ti*512+v]*s0[u-v]
        //   with sfr[k] = g[ti*512 + 511 - k] = forces[3584 - ti*512 + k]
        //   => out[u] = sum_k sfr[k]*shs2[u+k]   (shs2[511+j] = s0[j], zero-padded)
        int b2 = b - 512;                 // 0..63
        int ti = b2 >> 3, ap = b2 & 7;
        int half = tid >> 7;              // two audios per block
        int a = ap * 2 + half;
        int ltid = tid & 127;
        float* sfr  = sm + half * 1536;         // 512
        float* shs2 = sm + half * 1536 + 512;   // 1024

        for (int i = ltid; i < 512; i += 128)
            sfr[i] = forces[a * F + 3584 - (ti << 9) + i];
        for (int i = ltid; i < 1024; i += 128)
            shs2[i] = (i >= 511 && i < 1023) ? g_s0[a * 512 + i - 511] : 0.f;
        __syncthreads();

        int base = ltid * 4;
        float a0 = 0.f, a1 = 0.f, a2 = 0.f, a3 = 0.f;
        float4 sc = *(const float4*)(shs2 + base);
        #pragma unroll 4
        for (int k = 0; k < 512; k += 4) {
            float4 f4 = *(const float4*)(sfr + k);
            float4 sn = *(const float4*)(shs2 + base + k + 4);
            a0 = fmaf(f4.x, sc.x, a0); a1 = fmaf(f4.x, sc.y, a1); a2 = fmaf(f4.x, sc.z, a2); a3 = fmaf(f4.x, sc.w, a3);
            a0 = fmaf(f4.y, sc.y, a0); a1 = fmaf(f4.y, sc.z, a1); a2 = fmaf(f4.y, sc.w, a2); a3 = fmaf(f4.y, sn.x, a3);
            a0 = fmaf(f4.z, sc.z, a0); a1 = fmaf(f4.z, sc.w, a1); a2 = fmaf(f4.z, sn.x, a2); a3 = fmaf(f4.z, sn.y, a3);
            a0 = fmaf(f4.w, sc.w, a0); a1 = fmaf(f4.w, sn.x, a1); a2 = fmaf(f4.w, sn.y, a2); a3 = fmaf(f4.w, sn.z, a3);
            sc = sn;
        }
        float* dp = g_dpart + a * F + (ti << 9) + base;
        dp[0] = a0; dp[1] = a1; dp[2] = a2; dp[3] = a3;
    }
}

// ---------------- K4: prefix over lag chunks, fold amp ----------------
__global__ void k_prefix()
{
    int i = blockIdx.x * 256 + threadIdx.x;   // 1024 (m,a) pairs
    int m = i >> 4, a = i & 15;
    float am = g_amp[a * MODES + m];
    float A = 0.f, B = 0.f;
    #pragma unroll
    for (int c = 0; c < 8; c++) {
        float2 p = g_ABp[i * 8 + c];
        A += p.x; B += p.y;
        g_cum[c * 1024 + m * AUD + a] = make_float2(am * A, am * B);
    }
}

// ---------------- K5: unified output GEMM ----------------
__global__ void __launch_bounds__(128) k_out(float* __restrict__ out)
{
    __shared__ float2 shc[MODES * AUD];
    int b = blockIdx.x, tid = threadIdx.x;
    int t = b * 128 + tid;
    int ti = b >> 2;
    int cc = ti < 8 ? ti : 8;

    float acc[AUD];
    #pragma unroll
    for (int a = 0; a < AUD; a++) acc[a] = 0.f;

    if (cc > 0) {
        for (int i = tid; i < MODES * AUD; i += 128)
            shc[i] = g_cum[(cc - 1) * 1024 + i];
        __syncthreads();
        const float4* shc4 = (const float4*)shc;
        #pragma unroll 8
        for (int m = 0; m < MODES; m++) {
            float ps = g_Ps[m * T + t];
            float pc = g_Pc[m * T + t];
            #pragma unroll
            for (int aa = 0; aa < 8; aa++) {
                float4 v = shc4[m * 8 + aa];
                acc[2 * aa]     = fmaf(ps, v.x, fmaf(-pc, v.y, acc[2 * aa]));
                acc[2 * aa + 1] = fmaf(ps, v.z, fmaf(-pc, v.w, acc[2 * aa + 1]));
            }
        }
    }
    if (ti < 8) {
        #pragma unroll
        for (int a = 0; a < AUD; a++)
            acc[a] += g_dpart[a * F + t];
    }
    #pragma unroll
    for (int a = 0; a < AUD; a++)
        out[a * T + t] = acc[a];
}

// ---------------- launch ----------------
extern "C" void kernel_launch(void* const* d_in, const int* in_sizes, int n_in,
                              void* d_out, int out_size)
{
    const float* freq   = (const float*)d_in[0];
    const float* ampv   = (const float*)d_in[1];
    const float* ap     = (const float*)d_in[2];
    const float* bp     = (const float*)d_in[3];
    const float* forces = (const float*)d_in[4];
    float* out = (float*)d_out;

    k_tables<<<MODES, 128>>>(freq, ampv, ap, bp);
    k_fill<<<9218, 256>>>();
    k_chunks<<<576, 256>>>(forces);
    k_prefix<<<4, 256>>>();
    k_out<<<256, 128>>>(out);
}